// round 16
// baseline (speedup 1.0000x reference)
#include <cuda_runtime.h>
#include <cuda_fp16.h>
#include <math.h>
#include <stdint.h>

// ---------------- problem constants ----------------
#define BATCH 4
#define T     8192
#define H     1024
#define E     8
#define F     2048

// ---------------- GEMM tiling: CTA 128x128xK32, 4 warps (2x2), warp tile 64x64 ----------------
#define MT 128
#define NT 128
#define KT 32
#define NSTG 4
#define A_STRIDE 40     // fp16 per A smem row (32 + 8 pad)
#define B_STRIDE 136    // fp16 per B smem row (128 + 8 pad)
#define A_STAGE_BYTES (MT * A_STRIDE * 2)   // 10240
#define B_STAGE_BYTES (KT * B_STRIDE * 2)   // 8704
#define STAGE_BYTES (A_STAGE_BYTES + B_STAGE_BYTES)  // 18944
#define SMEM_DYN (NSTG * STAGE_BYTES)                // 75776

// prep kernel geometry: router + both weight converts
#define RB      (T / 8)                 // 1024 router blocks (8 tokens each)
#define N4W     (E * H * F / 4)         // 4194304 float4 per weight tensor
#define NPAIR   (N4W / 2)               // 2097152 float4-pairs per weight
#define CVTB    (NPAIR / 1024)          // 2048 blocks per weight (256 thr, 4 pairs each)

// ---------------- scratch (static device globals) ----------------
__device__ __half g_xh[(size_t)T * H];
__device__ __half g_w1h[(size_t)E * H * F];
__device__ __half g_w2h[(size_t)E * F * H];
__device__ __half g_Hact[(size_t)E * T * F];
__device__ __half g_Yh[(size_t)E * T * H];    // GEMM2 output, fp16
__device__ int    g_tok[E * T];
__device__ int    g_cnt[E];                    // zero-init; reset by k_combine tail
__device__ int    g_pair[T * 2];
__device__ int    g_pexp[T * 2];
__device__ float  g_loss[2];                   // zero-init; reset by k_combine tail

// ---------------- PTX helpers (sm_80+ only) ----------------
__device__ __forceinline__ uint32_t smem_u32(const void* p) {
    uint32_t a;
    asm("{ .reg .u64 t; cvta.to.shared.u64 t, %1; cvt.u32.u64 %0, t; }"
        : "=r"(a) : "l"(p));
    return a;
}
__device__ __forceinline__ void cp_async16(uint32_t dst, const void* src, uint32_t src_size) {
    asm volatile("cp.async.cg.shared.global [%0], [%1], 16, %2;"
                 :: "r"(dst), "l"(src), "r"(src_size));
}
#define CP_COMMIT() asm volatile("cp.async.commit_group;")
#define CP_WAIT2()  asm volatile("cp.async.wait_group 2;")

__device__ __forceinline__ void ldsm_x4(uint32_t& r0, uint32_t& r1, uint32_t& r2, uint32_t& r3,
                                        uint32_t addr) {
    asm volatile("ldmatrix.sync.aligned.m8n8.x4.shared.b16 {%0,%1,%2,%3}, [%4];"
                 : "=r"(r0), "=r"(r1), "=r"(r2), "=r"(r3) : "r"(addr));
}
__device__ __forceinline__ void ldsm_x4_t(uint32_t& r0, uint32_t& r1, uint32_t& r2, uint32_t& r3,
                                          uint32_t addr) {
    asm volatile("ldmatrix.sync.aligned.m8n8.x4.trans.shared.b16 {%0,%1,%2,%3}, [%4];"
                 : "=r"(r0), "=r"(r1), "=r"(r2), "=r"(r3) : "r"(addr));
}
__device__ __forceinline__ void mma_f16(float* c, const uint32_t* a, uint32_t b0, uint32_t b1) {
    asm volatile("mma.sync.aligned.m16n8k16.row.col.f32.f16.f16.f32 "
                 "{%0,%1,%2,%3}, {%4,%5,%6,%7}, {%8,%9}, {%0,%1,%2,%3};"
                 : "+f"(c[0]), "+f"(c[1]), "+f"(c[2]), "+f"(c[3])
                 : "r"(a[0]), "r"(a[1]), "r"(a[2]), "r"(a[3]), "r"(b0), "r"(b1));
}

// fast silu: v * 1/(1+e^-v) with MUFU (error ~2ulp, << fp16 quantization)
__device__ __forceinline__ float fast_silu(float v) {
    return __fdividef(v, 1.0f + __expf(-v));
}

// convert 4 float4-pairs -> 4 uint4 (8 fp16 each); tid-strided
__device__ __forceinline__ void cvt_pairs(const float4* __restrict__ src,
                                          uint4* __restrict__ dst,
                                          int pbase, int stride) {
    float4 v[8];
#pragma unroll
    for (int p = 0; p < 4; p++) {
        int ip = pbase + p * stride;
        v[2 * p]     = src[2 * ip];
        v[2 * p + 1] = src[2 * ip + 1];
    }
#pragma unroll
    for (int p = 0; p < 4; p++) {
        int ip = pbase + p * stride;
        __half2 h0 = __floats2half2_rn(v[2 * p].x, v[2 * p].y);
        __half2 h1 = __floats2half2_rn(v[2 * p].z, v[2 * p].w);
        __half2 h2 = __floats2half2_rn(v[2 * p + 1].x, v[2 * p + 1].y);
        __half2 h3 = __floats2half2_rn(v[2 * p + 1].z, v[2 * p + 1].w);
        uint4 pk;
        pk.x = *(uint32_t*)&h0;
        pk.y = *(uint32_t*)&h1;
        pk.z = *(uint32_t*)&h2;
        pk.w = *(uint32_t*)&h3;
        dst[ip] = pk;
    }
}

// fragment set for one k-group (K=16): A 64x16, B 16x64
struct Frag {
    uint32_t a[4][4];
    uint32_t b[4][4];
};

struct LdsmOff {
    uint32_t aoff;
    uint32_t boff;
};

__device__ __forceinline__ LdsmOff make_off(int lane, int wm, int wn) {
    LdsmOff o;
    o.aoff = (uint32_t)((wm * 64 + (lane & 15)) * (A_STRIDE * 2) + (lane >> 4) * 16);
    o.boff = (uint32_t)(((lane & 7) + ((lane >> 3) & 1) * 8) * (B_STRIDE * 2)
                        + (wn * 64 + (lane >> 4) * 8) * 2);
    return o;
}

__device__ __forceinline__ void load_frags(Frag& f, uint32_t aS, uint32_t bS,
                                           const LdsmOff& o, int ks) {
#pragma unroll
    for (int mf = 0; mf < 4; mf++)
        ldsm_x4(f.a[mf][0], f.a[mf][1], f.a[mf][2], f.a[mf][3],
                aS + o.aoff + mf * (16 * A_STRIDE * 2) + ks * 32);
#pragma unroll
    for (int np = 0; np < 4; np++)
        ldsm_x4_t(f.b[np][0], f.b[np][1], f.b[np][2], f.b[np][3],
                  bS + o.boff + ks * (16 * B_STRIDE * 2) + np * 32);
}

#define MMA_ALL(cfrag, f) do { \
    _Pragma("unroll") \
    for (int mf = 0; mf < 4; mf++) \
        _Pragma("unroll") \
        for (int nf = 0; nf < 8; nf++) \
            mma_f16(cfrag[mf][nf], (f).a[mf], \
                    (f).b[nf >> 1][(nf & 1) * 2], (f).b[nf >> 1][(nf & 1) * 2 + 1]); \
} while (0)

// ---------------- prep: router (blocks [0,RB)) + w1/w2 convert (rest) ----------------
__global__ void k_prep(const float* __restrict__ x,
                       const float* __restrict__ rw,
                       const float4* __restrict__ w1,
                       const float4* __restrict__ w2) {
    if (blockIdx.x >= RB) {
        int cb = blockIdx.x - RB;
        const float4* src = (cb < CVTB) ? w1 : w2;
        uint4* dst = (cb < CVTB) ? (uint4*)g_w1h : (uint4*)g_w2h;
        int blk = (cb < CVTB) ? cb : cb - CVTB;
        cvt_pairs(src, dst, blk * 1024 + threadIdx.x, 256);
        return;
    }

    // ---- router: one warp per token; also emits xh ----
    __shared__ float sw[E * H];
    for (int i = threadIdx.x; i < E * H; i += blockDim.x) sw[i] = rw[i];
    __syncthreads();

    int lane = threadIdx.x & 31;
    int warp = threadIdx.x >> 5;
    int t = blockIdx.x * 8 + warp;

    float xr[32];
    const float* xp = x + (size_t)t * H;
#pragma unroll
    for (int i = 0; i < 32; i++) xr[i] = xp[lane + 32 * i];

    __half* xo = g_xh + (size_t)t * H;
#pragma unroll
    for (int i = 0; i < 32; i++) xo[lane + 32 * i] = __float2half_rn(xr[i]);

    float lg[E];
#pragma unroll
    for (int e = 0; e < E; e++) {
        const float* w = sw + e * H;
        float s = 0.0f;
#pragma unroll
        for (int i = 0; i < 32; i++) s += xr[i] * w[lane + 32 * i];
#pragma unroll
        for (int o = 16; o > 0; o >>= 1) s += __shfl_xor_sync(0xffffffffu, s, o);
        lg[e] = s;
    }

    if (lane == 0) {
        float m = lg[0];
#pragma unroll
        for (int e = 1; e < E; e++) m = fmaxf(m, lg[e]);
        float se = 0.0f, sl = 0.0f, z = 0.0f;
#pragma unroll
        for (int e = 0; e < E; e++) {
            se += expf(lg[e] - m); sl += lg[e]; z += lg[e] * lg[e];
        }
        float lse = m + logf(se);
        float sumlogp = sl - (float)E * lse;
        float aux = -2.0794415416798357f - sumlogp * (1.0f / (float)E);
        atomicAdd(&g_loss[0], aux);
        atomicAdd(&g_loss[1], z);

        int e0 = 0;
#pragma unroll
        for (int e = 1; e < E; e++) if (lg[e] > lg[e0]) e0 = e;
        int e1 = (e0 == 0) ? 1 : 0;
#pragma unroll
        for (int e = 0; e < E; e++)
            if (e != e0 && lg[e] > lg[e1]) e1 = e;

        int es[2] = {e0, e1};
#pragma unroll
        for (int k = 0; k < 2; k++) {
            int e = es[k];
            int pos = atomicAdd(&g_cnt[e], 1);
            g_tok[e * T + pos] = t;
            g_pair[t * 2 + k] = e * T + pos;
            g_pexp[t * 2 + k] = e;
        }
    }
}

// ---------------- GEMM1: Hact = silu( gather(xh) @ w1h[e] + b1[e] ) ----------------
__global__ __launch_bounds__(128, 2) void k_gemm1(const float* __restrict__ b1) {
    extern __shared__ char smem[];
    __shared__ int stok[MT];

    int e = blockIdx.z;
    int ne = g_cnt[e];
    int gm = blockIdx.y * MT;
    if (gm >= ne) return;
    int gn = blockIdx.x * NT;

    int tid = threadIdx.x, lane = tid & 31, wid = tid >> 5;
    int wm = wid & 1, wn = wid >> 1;   // 2 x 2 warps; warp tile 64x64

    if (tid < MT) stok[tid] = (gm + tid < ne) ? g_tok[e * T + gm + tid] : -1;
    __syncthreads();

    const __half* wB = g_w1h + (size_t)e * H * F;
    uint32_t sbase = smem_u32(smem);
    LdsmOff off = make_off(lane, wm, wn);

    float cfrag[4][8][4];
#pragma unroll
    for (int i = 0; i < 4; i++)
#pragma unroll
        for (int j = 0; j < 8; j++)
#pragma unroll
            for (int k = 0; k < 4; k++) cfrag[i][j][k] = 0.0f;

    const int k_iters = H / KT;  // 32

    auto load_stage = [&](int buf, int k0) {
        uint32_t aB = sbase + buf * STAGE_BYTES;
        uint32_t bB = aB + A_STAGE_BYTES;
#pragma unroll
        for (int q = 0; q < 4; q++) {
            int g = tid + q * 128;
            int r = g >> 2, cg = g & 3;
            int tk = stok[r];
            const __half* src = g_xh + (size_t)(tk < 0 ? 0 : tk) * H + k0 + cg * 8;
            cp_async16(aB + r * (A_STRIDE * 2) + cg * 16, src, tk >= 0 ? 16u : 0u);
        }
#pragma unroll
        for (int q = 0; q < 4; q++) {
            int g = tid + q * 128;
            int r = g >> 4, cg = g & 15;
            const __half* src = wB + (size_t)(k0 + r) * F + gn + cg * 8;
            cp_async16(bB + r * (B_STRIDE * 2) + cg * 16, src, 16u);
        }
    };

    load_stage(0, 0); CP_COMMIT();
    load_stage(1, KT); CP_COMMIT();
    load_stage(2, 2 * KT); CP_COMMIT();
    CP_WAIT2(); __syncthreads();

    Frag fr[2];
    load_frags(fr[0], sbase, sbase + A_STAGE_BYTES, off, 0);

    for (int it = 0; it < k_iters; it++) {
        uint32_t aC = sbase + (it % NSTG) * STAGE_BYTES;
        uint32_t bC = aC + A_STAGE_BYTES;
        uint32_t aN = sbase + ((it + 1) % NSTG) * STAGE_BYTES;
        uint32_t bN = aN + A_STAGE_BYTES;

        load_frags(fr[1], aC, bC, off, 1);
        if (it + 3 < k_iters) load_stage((it + 3) % NSTG, (it + 3) * KT);
        CP_COMMIT();
        MMA_ALL(cfrag, fr[0]);

        if (it + 1 < k_iters) {
            CP_WAIT2(); __syncthreads();
            load_frags(fr[0], aN, bN, off, 0);
        }
        MMA_ALL(cfrag, fr[1]);
    }

#pragma unroll
    for (int nf = 0; nf < 8; nf++) {
        int col = gn + wn * 64 + nf * 8 + (lane & 3) * 2;
        float bias0 = b1[e * F + col];
        float bias1 = b1[e * F + col + 1];
#pragma unroll
        for (int mf = 0; mf < 4; mf++) {
            int r0 = gm + wm * 64 + mf * 16 + (lane >> 2);
            float* c = cfrag[mf][nf];
            if (r0 < ne) {
                float v0 = fast_silu(c[0] + bias0);
                float v1 = fast_silu(c[1] + bias1);
                *(__half2*)(g_Hact + ((size_t)e * T + r0) * F + col) =
                    __floats2half2_rn(v0, v1);
            }
            if (r0 + 8 < ne) {
                float v2 = fast_silu(c[2] + bias0);
                float v3 = fast_silu(c[3] + bias1);
                *(__half2*)(g_Hact + ((size_t)e * T + r0 + 8) * F + col) =
                    __floats2half2_rn(v2, v3);
            }
        }
    }
}

// ---------------- GEMM2: Yh = Hact @ w2h[e] (fp16 out) ----------------
__global__ __launch_bounds__(128, 2) void k_gemm2() {
    extern __shared__ char smem[];

    int e = blockIdx.z;
    int ne = g_cnt[e];
    int gm = blockIdx.y * MT;
    if (gm >= ne) return;
    int gn = blockIdx.x * NT;

    int tid = threadIdx.x, lane = tid & 31, wid = tid >> 5;
    int wm = wid & 1, wn = wid >> 1;

    const __half* aSrc = g_Hact + ((size_t)e * T + gm) * F;
    const __half* wB = g_w2h + (size_t)e * F * H;
    uint32_t sbase = smem_u32(smem);
    LdsmOff off = make_off(lane, wm, wn);

    float cfrag[4][8][4];
#pragma unroll
    for (int i = 0; i < 4; i++)
#pragma unroll
        for (int j = 0; j < 8; j++)
#pragma unroll
            for (int k = 0; k < 4; k++) cfrag[i][j][k] = 0.0f;

    const int k_iters = F / KT;  // 64

    auto load_stage = [&](int buf, int k0) {
        uint32_t aB = sbase + buf * STAGE_BYTES;
        uint32_t bB = aB + A_STAGE_BYTES;
#pragma unroll
        for (int q = 0; q < 4; q++) {
            int g = tid + q * 128;
            int r = g >> 2, cg = g & 3;
            const __half* src = aSrc + (size_t)r * F + k0 + cg * 8;
            cp_async16(aB + r * (A_STRIDE * 2) + cg * 16, src, 16u);
        }
#pragma unroll
        for (int q = 0; q < 4; q++) {
            int g = tid + q * 128;
            int r = g >> 4, cg = g & 15;
            const __half* src = wB + (size_t)(k0 + r) * H + gn + cg * 8;
            cp_async16(bB + r * (B_STRIDE * 2) + cg * 16, src, 16u);
        }
    };

    load_stage(0, 0); CP_COMMIT();
    load_stage(1, KT); CP_COMMIT();
    load_stage(2, 2 * KT); CP_COMMIT();
    CP_WAIT2(); __syncthreads();

    Frag fr[2];
    load_frags(fr[0], sbase, sbase + A_STAGE_BYTES, off, 0);

    for (int it = 0; it < k_iters; it++) {
        uint32_t aC = sbase + (it % NSTG) * STAGE_BYTES;
        uint32_t bC = aC + A_STAGE_BYTES;
        uint32_t aN = sbase + ((it + 1) % NSTG) * STAGE_BYTES;
        uint32_t bN = aN + A_STAGE_BYTES;

        load_frags(fr[1], aC, bC, off, 1);
        if (it + 3 < k_iters) load_stage((it + 3) % NSTG, (it + 3) * KT);
        CP_COMMIT();
        MMA_ALL(cfrag, fr[0]);

        if (it + 1 < k_iters) {
            CP_WAIT2(); __syncthreads();
            load_frags(fr[0], aN, bN, off, 0);
        }
        MMA_ALL(cfrag, fr[1]);
    }

#pragma unroll
    for (int nf = 0; nf < 8; nf++) {
        int col = gn + wn * 64 + nf * 8 + (lane & 3) * 2;
#pragma unroll
        for (int mf = 0; mf < 4; mf++) {
            int r0 = gm + wm * 64 + mf * 16 + (lane >> 2);
            float* c = cfrag[mf][nf];
            if (r0 < ne) {
                *(__half2*)(g_Yh + ((size_t)e * T + r0) * H + col) =
                    __floats2half2_rn(c[0], c[1]);
            }
            if (r0 + 8 < ne) {
                *(__half2*)(g_Yh + ((size_t)e * T + r0 + 8) * H + col) =
                    __floats2half2_rn(c[2], c[3]);
            }
        }
    }
}

// ---------------- combine: out = Yh[p0] + Yh[p1] + b2[e0] + b2[e1]; loss + reset ----------------
__global__ void k_combine(const float* __restrict__ b2,
                          float* __restrict__ out, int out_size) {
    if (blockIdx.x == 0 && threadIdx.x == 0) {
        if (out_size > T * H) {
            float aux = g_loss[0] * (0.001f / (float)BATCH);
            float z   = g_loss[1] * (0.001f / (float)(T * E));
            out[T * H] = aux + z;
        }
        // reset for next invocation (graph replay): counters must start at 0
        g_loss[0] = 0.0f; g_loss[1] = 0.0f;
#pragma unroll
        for (int e = 0; e < E; e++) g_cnt[e] = 0;
    }

    int i = threadIdx.x;  // 256 threads, 4 cols each, 2 tokens per block
#pragma unroll
    for (int q = 0; q < 2; q++) {
        int t = blockIdx.x * 2 + q;
        int p0 = g_pair[2 * t], p1 = g_pair[2 * t + 1];
        int e0 = g_pexp[2 * t], e1 = g_pexp[2 * t + 1];

        uint2 ya = *(const uint2*)(g_Yh + (size_t)p0 * H + i * 4);
        uint2 yb = *(const uint2*)(g_Yh + (size_t)p1 * H + i * 4);
        float4 ca = *(const float4*)(b2 + (size_t)e0 * H + i * 4);
        float4 cb = *(const float4*)(b2 + (size_t)e1 * H + i * 4);

        float2 a0 = __half22float2(*(__half2*)&ya.x);
        float2 a1 = __half22float2(*(__half2*)&ya.y);
        float2 b0 = __half22float2(*(__half2*)&yb.x);
        float2 b1 = __half22float2(*(__half2*)&yb.y);

        float4 o;
        o.x = a0.x + b0.x + ca.x + cb.x;
        o.y = a0.y + b0.y + ca.y + cb.y;
        o.z = a1.x + b1.x + ca.z + cb.z;
        o.w = a1.y + b1.y + ca.w + cb.w;
        *(float4*)(out + (size_t)t * H + i * 4) = o;
    }
}

extern "C" void kernel_launch(void* const* d_in, const int* in_sizes, int n_in,
                              void* d_out, int out_size) {
    const float* x  = (const float*)d_in[0];
    const float* rw = (const float*)d_in[1];
    const float* w1 = (const float*)d_in[2];
    const float* b1 = (const float*)d_in[3];
    const float* w2 = (const float*)d_in[4];
    const float* b2 = (const float*)d_in[5];
    float* out = (float*)d_out;

    cudaFuncSetAttribute(k_gemm1, cudaFuncAttributeMaxDynamicSharedMemorySize, SMEM_DYN);
    cudaFuncSetAttribute(k_gemm2, cudaFuncAttributeMaxDynamicSharedMemorySize, SMEM_DYN);

    k_prep<<<RB + 2 * CVTB, 256>>>(x, rw, (const float4*)w1, (const float4*)w2);

    k_gemm1<<<dim3(F / NT, T / MT, E), 128, SMEM_DYN>>>(b1);
    k_gemm2<<<dim3(H / NT, T / MT, E), 128, SMEM_DYN>>>();

    k_combine<<<T / 2, 256>>>(b2, out, out_size);
}

// round 17
// speedup vs baseline: 1.4789x; 1.4789x over previous
#include <cuda_runtime.h>
#include <cuda_fp16.h>
#include <math.h>
#include <stdint.h>

// ---------------- problem constants ----------------
#define BATCH 4
#define T     8192
#define H     1024
#define E     8
#define F     2048

// ---------------- GEMM tiling: CTA 128x128xK32, 4 warps (2x2), warp tile 64x64 ----------------
#define MT 128
#define NT 128
#define KT 32
#define NSTG 4
#define A_STRIDE 40     // fp16 per A smem row (32 + 8 pad)
#define B_STRIDE 136    // fp16 per B smem row (128 + 8 pad)
#define A_STAGE_BYTES (MT * A_STRIDE * 2)   // 10240
#define B_STAGE_BYTES (KT * B_STRIDE * 2)   // 8704
#define STAGE_BYTES (A_STAGE_BYTES + B_STAGE_BYTES)  // 18944
#define SMEM_DYN (NSTG * STAGE_BYTES)                // 75776

// prep kernel geometry: router + both weight converts
#define RB      (T / 8)                 // 1024 router blocks (8 tokens each)
#define N4W     (E * H * F / 4)         // 4194304 float4 per weight tensor
#define NPAIR   (N4W / 2)               // 2097152 float4-pairs per weight
#define CVTB    (NPAIR / 1024)          // 2048 blocks per weight (256 thr, 4 pairs each)

// ---------------- scratch (static device globals) ----------------
__device__ __half g_xh[(size_t)T * H];
__device__ __half g_w1h[(size_t)E * H * F];
__device__ __half g_w2h[(size_t)E * F * H];
__device__ __half g_Hact[(size_t)E * T * F];
__device__ __half g_Yh[(size_t)E * T * H];    // GEMM2 output, fp16
__device__ int    g_tok[E * T];
__device__ int    g_cnt[E];                    // zero-init; reset by k_combine tail
__device__ int    g_pair[T * 2];
__device__ int    g_pexp[T * 2];
__device__ float  g_loss[2];                   // zero-init; reset by k_combine tail

// ---------------- PTX helpers (sm_80+ only) ----------------
__device__ __forceinline__ uint32_t smem_u32(const void* p) {
    uint32_t a;
    asm("{ .reg .u64 t; cvta.to.shared.u64 t, %1; cvt.u32.u64 %0, t; }"
        : "=r"(a) : "l"(p));
    return a;
}
__device__ __forceinline__ void cp_async16(uint32_t dst, const void* src, uint32_t src_size) {
    asm volatile("cp.async.cg.shared.global [%0], [%1], 16, %2;"
                 :: "r"(dst), "l"(src), "r"(src_size));
}
#define CP_COMMIT() asm volatile("cp.async.commit_group;")
#define CP_WAIT2()  asm volatile("cp.async.wait_group 2;")

__device__ __forceinline__ void ldsm_x4(uint32_t& r0, uint32_t& r1, uint32_t& r2, uint32_t& r3,
                                        uint32_t addr) {
    asm volatile("ldmatrix.sync.aligned.m8n8.x4.shared.b16 {%0,%1,%2,%3}, [%4];"
                 : "=r"(r0), "=r"(r1), "=r"(r2), "=r"(r3) : "r"(addr));
}
__device__ __forceinline__ void ldsm_x4_t(uint32_t& r0, uint32_t& r1, uint32_t& r2, uint32_t& r3,
                                          uint32_t addr) {
    asm volatile("ldmatrix.sync.aligned.m8n8.x4.trans.shared.b16 {%0,%1,%2,%3}, [%4];"
                 : "=r"(r0), "=r"(r1), "=r"(r2), "=r"(r3) : "r"(addr));
}
__device__ __forceinline__ void mma_f16(float* c, const uint32_t* a, uint32_t b0, uint32_t b1) {
    asm volatile("mma.sync.aligned.m16n8k16.row.col.f32.f16.f16.f32 "
                 "{%0,%1,%2,%3}, {%4,%5,%6,%7}, {%8,%9}, {%0,%1,%2,%3};"
                 : "+f"(c[0]), "+f"(c[1]), "+f"(c[2]), "+f"(c[3])
                 : "r"(a[0]), "r"(a[1]), "r"(a[2]), "r"(a[3]), "r"(b0), "r"(b1));
}

// fast silu: v * 1/(1+e^-v) with MUFU (error ~2ulp, << fp16 quantization)
__device__ __forceinline__ float fast_silu(float v) {
    return __fdividef(v, 1.0f + __expf(-v));
}

// convert 4 float4-pairs -> 4 uint4 (8 fp16 each); tid-strided
__device__ __forceinline__ void cvt_pairs(const float4* __restrict__ src,
                                          uint4* __restrict__ dst,
                                          int pbase, int stride) {
    float4 v[8];
#pragma unroll
    for (int p = 0; p < 4; p++) {
        int ip = pbase + p * stride;
        v[2 * p]     = src[2 * ip];
        v[2 * p + 1] = src[2 * ip + 1];
    }
#pragma unroll
    for (int p = 0; p < 4; p++) {
        int ip = pbase + p * stride;
        __half2 h0 = __floats2half2_rn(v[2 * p].x, v[2 * p].y);
        __half2 h1 = __floats2half2_rn(v[2 * p].z, v[2 * p].w);
        __half2 h2 = __floats2half2_rn(v[2 * p + 1].x, v[2 * p + 1].y);
        __half2 h3 = __floats2half2_rn(v[2 * p + 1].z, v[2 * p + 1].w);
        uint4 pk;
        pk.x = *(uint32_t*)&h0;
        pk.y = *(uint32_t*)&h1;
        pk.z = *(uint32_t*)&h2;
        pk.w = *(uint32_t*)&h3;
        dst[ip] = pk;
    }
}

// fragment set for one k-group (K=16): A 64x16, B 16x64
struct Frag {
    uint32_t a[4][4];
    uint32_t b[4][4];
};

struct LdsmOff {
    uint32_t aoff;
    uint32_t boff;
};

__device__ __forceinline__ LdsmOff make_off(int lane, int wm, int wn) {
    LdsmOff o;
    o.aoff = (uint32_t)((wm * 64 + (lane & 15)) * (A_STRIDE * 2) + (lane >> 4) * 16);
    o.boff = (uint32_t)(((lane & 7) + ((lane >> 3) & 1) * 8) * (B_STRIDE * 2)
                        + (wn * 64 + (lane >> 4) * 8) * 2);
    return o;
}

__device__ __forceinline__ void load_frags(Frag& f, uint32_t aS, uint32_t bS,
                                           const LdsmOff& o, int ks) {
#pragma unroll
    for (int mf = 0; mf < 4; mf++)
        ldsm_x4(f.a[mf][0], f.a[mf][1], f.a[mf][2], f.a[mf][3],
                aS + o.aoff + mf * (16 * A_STRIDE * 2) + ks * 32);
#pragma unroll
    for (int np = 0; np < 4; np++)
        ldsm_x4_t(f.b[np][0], f.b[np][1], f.b[np][2], f.b[np][3],
                  bS + o.boff + ks * (16 * B_STRIDE * 2) + np * 32);
}

#define MMA_ALL(cfrag, f) do { \
    _Pragma("unroll") \
    for (int mf = 0; mf < 4; mf++) \
        _Pragma("unroll") \
        for (int nf = 0; nf < 8; nf++) \
            mma_f16(cfrag[mf][nf], (f).a[mf], \
                    (f).b[nf >> 1][(nf & 1) * 2], (f).b[nf >> 1][(nf & 1) * 2 + 1]); \
} while (0)

// ---------------- prep: router (blocks [0,RB)) + w1/w2 convert (rest) ----------------
__global__ void k_prep(const float* __restrict__ x,
                       const float* __restrict__ rw,
                       const float4* __restrict__ w1,
                       const float4* __restrict__ w2) {
    if (blockIdx.x >= RB) {
        int cb = blockIdx.x - RB;
        const float4* src = (cb < CVTB) ? w1 : w2;
        uint4* dst = (cb < CVTB) ? (uint4*)g_w1h : (uint4*)g_w2h;
        int blk = (cb < CVTB) ? cb : cb - CVTB;
        cvt_pairs(src, dst, blk * 1024 + threadIdx.x, 256);
        return;
    }

    // ---- router: one warp per token; also emits xh ----
    __shared__ float sw[E * H];
    for (int i = threadIdx.x; i < E * H; i += blockDim.x) sw[i] = rw[i];
    __syncthreads();

    int lane = threadIdx.x & 31;
    int warp = threadIdx.x >> 5;
    int t = blockIdx.x * 8 + warp;

    float xr[32];
    const float* xp = x + (size_t)t * H;
#pragma unroll
    for (int i = 0; i < 32; i++) xr[i] = xp[lane + 32 * i];

    __half* xo = g_xh + (size_t)t * H;
#pragma unroll
    for (int i = 0; i < 32; i++) xo[lane + 32 * i] = __float2half_rn(xr[i]);

    float lg[E];
#pragma unroll
    for (int e = 0; e < E; e++) {
        const float* w = sw + e * H;
        float s = 0.0f;
#pragma unroll
        for (int i = 0; i < 32; i++) s += xr[i] * w[lane + 32 * i];
#pragma unroll
        for (int o = 16; o > 0; o >>= 1) s += __shfl_xor_sync(0xffffffffu, s, o);
        lg[e] = s;
    }

    if (lane == 0) {
        float m = lg[0];
#pragma unroll
        for (int e = 1; e < E; e++) m = fmaxf(m, lg[e]);
        float se = 0.0f, sl = 0.0f, z = 0.0f;
#pragma unroll
        for (int e = 0; e < E; e++) {
            se += expf(lg[e] - m); sl += lg[e]; z += lg[e] * lg[e];
        }
        float lse = m + logf(se);
        float sumlogp = sl - (float)E * lse;
        float aux = -2.0794415416798357f - sumlogp * (1.0f / (float)E);
        atomicAdd(&g_loss[0], aux);
        atomicAdd(&g_loss[1], z);

        int e0 = 0;
#pragma unroll
        for (int e = 1; e < E; e++) if (lg[e] > lg[e0]) e0 = e;
        int e1 = (e0 == 0) ? 1 : 0;
#pragma unroll
        for (int e = 0; e < E; e++)
            if (e != e0 && lg[e] > lg[e1]) e1 = e;

        int es[2] = {e0, e1};
#pragma unroll
        for (int k = 0; k < 2; k++) {
            int e = es[k];
            int pos = atomicAdd(&g_cnt[e], 1);
            g_tok[e * T + pos] = t;
            g_pair[t * 2 + k] = e * T + pos;
            g_pexp[t * 2 + k] = e;
        }
    }
}

// ---------------- GEMM1: Hact = silu( gather(xh) @ w1h[e] + b1[e] ) ----------------
__global__ __launch_bounds__(128, 2) void k_gemm1(const float* __restrict__ b1) {
    extern __shared__ char smem[];
    __shared__ int stok[MT];

    int e = blockIdx.z;
    int ne = g_cnt[e];
    int gm = blockIdx.y * MT;
    if (gm >= ne) return;
    int gn = blockIdx.x * NT;

    int tid = threadIdx.x, lane = tid & 31, wid = tid >> 5;
    int wm = wid & 1, wn = wid >> 1;   // 2 x 2 warps; warp tile 64x64

    if (tid < MT) stok[tid] = (gm + tid < ne) ? g_tok[e * T + gm + tid] : -1;
    __syncthreads();

    const __half* wB = g_w1h + (size_t)e * H * F;
    uint32_t sbase = smem_u32(smem);
    LdsmOff off = make_off(lane, wm, wn);

    float cfrag[4][8][4];
#pragma unroll
    for (int i = 0; i < 4; i++)
#pragma unroll
        for (int j = 0; j < 8; j++)
#pragma unroll
            for (int k = 0; k < 4; k++) cfrag[i][j][k] = 0.0f;

    const int k_iters = H / KT;  // 32

    auto load_stage = [&](int buf, int k0) {
        uint32_t aB = sbase + buf * STAGE_BYTES;
        uint32_t bB = aB + A_STAGE_BYTES;
#pragma unroll
        for (int q = 0; q < 4; q++) {
            int g = tid + q * 128;
            int r = g >> 2, cg = g & 3;
            int tk = stok[r];
            const __half* src = g_xh + (size_t)(tk < 0 ? 0 : tk) * H + k0 + cg * 8;
            cp_async16(aB + r * (A_STRIDE * 2) + cg * 16, src, tk >= 0 ? 16u : 0u);
        }
#pragma unroll
        for (int q = 0; q < 4; q++) {
            int g = tid + q * 128;
            int r = g >> 4, cg = g & 15;
            const __half* src = wB + (size_t)(k0 + r) * F + gn + cg * 8;
            cp_async16(bB + r * (B_STRIDE * 2) + cg * 16, src, 16u);
        }
    };

    load_stage(0, 0); CP_COMMIT();
    load_stage(1, KT); CP_COMMIT();
    load_stage(2, 2 * KT); CP_COMMIT();
    CP_WAIT2(); __syncthreads();

    Frag fr[2];
    load_frags(fr[0], sbase, sbase + A_STAGE_BYTES, off, 0);

    for (int it = 0; it < k_iters; it++) {
        uint32_t aC = sbase + (it % NSTG) * STAGE_BYTES;
        uint32_t bC = aC + A_STAGE_BYTES;
        uint32_t aN = sbase + ((it + 1) % NSTG) * STAGE_BYTES;
        uint32_t bN = aN + A_STAGE_BYTES;

        load_frags(fr[1], aC, bC, off, 1);
        if (it + 3 < k_iters) load_stage((it + 3) % NSTG, (it + 3) * KT);
        CP_COMMIT();
        MMA_ALL(cfrag, fr[0]);

        if (it + 1 < k_iters) {
            CP_WAIT2(); __syncthreads();
            load_frags(fr[0], aN, bN, off, 0);
        }
        MMA_ALL(cfrag, fr[1]);
    }

#pragma unroll
    for (int nf = 0; nf < 8; nf++) {
        int col = gn + wn * 64 + nf * 8 + (lane & 3) * 2;
        float bias0 = b1[e * F + col];
        float bias1 = b1[e * F + col + 1];
#pragma unroll
        for (int mf = 0; mf < 4; mf++) {
            int r0 = gm + wm * 64 + mf * 16 + (lane >> 2);
            float* c = cfrag[mf][nf];
            if (r0 < ne) {
                float v0 = fast_silu(c[0] + bias0);
                float v1 = fast_silu(c[1] + bias1);
                *(__half2*)(g_Hact + ((size_t)e * T + r0) * F + col) =
                    __floats2half2_rn(v0, v1);
            }
            if (r0 + 8 < ne) {
                float v2 = fast_silu(c[2] + bias0);
                float v3 = fast_silu(c[3] + bias1);
                *(__half2*)(g_Hact + ((size_t)e * T + r0 + 8) * F + col) =
                    __floats2half2_rn(v2, v3);
            }
        }
    }
}

// ---------------- GEMM2: Yh = Hact @ w2h[e] (fp16 out) ----------------
__global__ __launch_bounds__(128, 2) void k_gemm2() {
    extern __shared__ char smem[];

    int e = blockIdx.z;
    int ne = g_cnt[e];
    int gm = blockIdx.y * MT;
    if (gm >= ne) return;
    int gn = blockIdx.x * NT;

    int tid = threadIdx.x, lane = tid & 31, wid = tid >> 5;
    int wm = wid & 1, wn = wid >> 1;

    const __half* aSrc = g_Hact + ((size_t)e * T + gm) * F;
    const __half* wB = g_w2h + (size_t)e * F * H;
    uint32_t sbase = smem_u32(smem);
    LdsmOff off = make_off(lane, wm, wn);

    float cfrag[4][8][4];
#pragma unroll
    for (int i = 0; i < 4; i++)
#pragma unroll
        for (int j = 0; j < 8; j++)
#pragma unroll
            for (int k = 0; k < 4; k++) cfrag[i][j][k] = 0.0f;

    const int k_iters = F / KT;  // 64

    auto load_stage = [&](int buf, int k0) {
        uint32_t aB = sbase + buf * STAGE_BYTES;
        uint32_t bB = aB + A_STAGE_BYTES;
#pragma unroll
        for (int q = 0; q < 4; q++) {
            int g = tid + q * 128;
            int r = g >> 2, cg = g & 3;
            const __half* src = aSrc + (size_t)r * F + k0 + cg * 8;
            cp_async16(aB + r * (A_STRIDE * 2) + cg * 16, src, 16u);
        }
#pragma unroll
        for (int q = 0; q < 4; q++) {
            int g = tid + q * 128;
            int r = g >> 4, cg = g & 15;
            const __half* src = wB + (size_t)(k0 + r) * H + gn + cg * 8;
            cp_async16(bB + r * (B_STRIDE * 2) + cg * 16, src, 16u);
        }
    };

    load_stage(0, 0); CP_COMMIT();
    load_stage(1, KT); CP_COMMIT();
    load_stage(2, 2 * KT); CP_COMMIT();
    CP_WAIT2(); __syncthreads();

    Frag fr[2];
    load_frags(fr[0], sbase, sbase + A_STAGE_BYTES, off, 0);

    for (int it = 0; it < k_iters; it++) {
        uint32_t aC = sbase + (it % NSTG) * STAGE_BYTES;
        uint32_t bC = aC + A_STAGE_BYTES;
        uint32_t aN = sbase + ((it + 1) % NSTG) * STAGE_BYTES;
        uint32_t bN = aN + A_STAGE_BYTES;

        load_frags(fr[1], aC, bC, off, 1);
        if (it + 3 < k_iters) load_stage((it + 3) % NSTG, (it + 3) * KT);
        CP_COMMIT();
        MMA_ALL(cfrag, fr[0]);

        if (it + 1 < k_iters) {
            CP_WAIT2(); __syncthreads();
            load_frags(fr[0], aN, bN, off, 0);
        }
        MMA_ALL(cfrag, fr[1]);
    }

#pragma unroll
    for (int nf = 0; nf < 8; nf++) {
        int col = gn + wn * 64 + nf * 8 + (lane & 3) * 2;
#pragma unroll
        for (int mf = 0; mf < 4; mf++) {
            int r0 = gm + wm * 64 + mf * 16 + (lane >> 2);
            float* c = cfrag[mf][nf];
            if (r0 < ne) {
                *(__half2*)(g_Yh + ((size_t)e * T + r0) * H + col) =
                    __floats2half2_rn(c[0], c[1]);
            }
            if (r0 + 8 < ne) {
                *(__half2*)(g_Yh + ((size_t)e * T + r0 + 8) * H + col) =
                    __floats2half2_rn(c[2], c[3]);
            }
        }
    }
}

// ---------------- combine: out = Yh[p0] + Yh[p1] + b2[e0] + b2[e1]; loss + reset ----------------
__global__ void k_combine(const float* __restrict__ b2,
                          float* __restrict__ out, int out_size) {
    if (blockIdx.x == 0 && threadIdx.x == 0) {
        if (out_size > T * H) {
            float aux = g_loss[0] * (0.001f / (float)BATCH);
            float z   = g_loss[1] * (0.001f / (float)(T * E));
            out[T * H] = aux + z;
        }
        // reset for next invocation (graph replay): counters must start at 0
        g_loss[0] = 0.0f; g_loss[1] = 0.0f;
#pragma unroll
        for (int e = 0; e < E; e++) g_cnt[e] = 0;
    }

    int i = threadIdx.x;  // 256 threads, 4 cols each, 2 tokens per block
#pragma unroll
    for (int q = 0; q < 2; q++) {
        int t = blockIdx.x * 2 + q;
        int p0 = g_pair[2 * t], p1 = g_pair[2 * t + 1];
        int e0 = g_pexp[2 * t], e1 = g_pexp[2 * t + 1];

        uint2 ya = *(const uint2*)(g_Yh + (size_t)p0 * H + i * 4);
        uint2 yb = *(const uint2*)(g_Yh + (size_t)p1 * H + i * 4);
        float4 ca = *(const float4*)(b2 + (size_t)e0 * H + i * 4);
        float4 cb = *(const float4*)(b2 + (size_t)e1 * H + i * 4);

        float2 a0 = __half22float2(*(__half2*)&ya.x);
        float2 a1 = __half22float2(*(__half2*)&ya.y);
        float2 b0 = __half22float2(*(__half2*)&yb.x);
        float2 b1 = __half22float2(*(__half2*)&yb.y);

        float4 o;
        o.x = a0.x + b0.x + ca.x + cb.x;
        o.y = a0.y + b0.y + ca.y + cb.y;
        o.z = a1.x + b1.x + ca.z + cb.z;
        o.w = a1.y + b1.y + ca.w + cb.w;
        *(float4*)(out + (size_t)t * H + i * 4) = o;
    }
}

extern "C" void kernel_launch(void* const* d_in, const int* in_sizes, int n_in,
                              void* d_out, int out_size) {
    const float* x  = (const float*)d_in[0];
    const float* rw = (const float*)d_in[1];
    const float* w1 = (const float*)d_in[2];
    const float* b1 = (const float*)d_in[3];
    const float* w2 = (const float*)d_in[4];
    const float* b2 = (const float*)d_in[5];
    float* out = (float*)d_out;

    cudaFuncSetAttribute(k_gemm1, cudaFuncAttributeMaxDynamicSharedMemorySize, SMEM_DYN);
    cudaFuncSetAttribute(k_gemm2, cudaFuncAttributeMaxDynamicSharedMemorySize, SMEM_DYN);

    k_prep<<<RB + 2 * CVTB, 256>>>(x, rw, (const float4*)w1, (const float4*)w2);

    k_gemm1<<<dim3(F / NT, T / MT, E), 128, SMEM_DYN>>>(b1);
    k_gemm2<<<dim3(H / NT, T / MT, E), 128, SMEM_DYN>>>();

    k_combine<<<T / 2, 256>>>(b2, out, out_size);
}